// round 14
// baseline (speedup 1.0000x reference)
#include <cuda_runtime.h>
#include <cuda_bf16.h>
#include <cstdint>

// ---------------- problem constants ----------------
#define NPTS  50000
#define HN    32
#define INF   128
#define MIDF  64
#define OUTF  256
#define KP    15
#define KPD   (KP*MIDF)      // 960
#define KPEXT 0.48f
#define BNEPS 1e-6f
#define SLOPE 0.1f

typedef unsigned long long ull;

// ---------------- helpers ----------------
__device__ __forceinline__ ull pack2(float x, float y) {
    ull r; asm("mov.b64 %0, {%1, %2};" : "=l"(r) : "f"(x), "f"(y)); return r;
}
__device__ __forceinline__ void unpack2(ull v, float& x, float& y) {
    asm("mov.b64 {%0, %1}, %2;" : "=f"(x), "=f"(y) : "l"(v));
}
__device__ __forceinline__ void ffma2(ull& d, ull a, ull b) {
    asm("fma.rn.f32x2 %0, %1, %2, %0;" : "+l"(d) : "l"(a), "l"(b));
}
__device__ __forceinline__ uint32_t smem_u32(const void* p) {
    uint32_t a;
    asm("{ .reg .u64 t; cvta.to.shared.u64 t, %1; cvt.u32.u64 %0, t; }" : "=r"(a) : "l"(p));
    return a;
}
__device__ __forceinline__ void cp_async16(uint32_t dst, const void* src, int szbytes) {
    asm volatile("cp.async.cg.shared.global [%0], [%1], 16, %2;"
                 :: "r"(dst), "l"(src), "r"(szbytes));
}
#define CP_COMMIT() asm volatile("cp.async.commit_group;" ::: "memory")
#define CP_WAIT1()  asm volatile("cp.async.wait_group 1;" ::: "memory")
#define CP_WAIT0()  asm volatile("cp.async.wait_group 0;" ::: "memory")

#define LDSM4(R, ADDR) \
    asm volatile("ldmatrix.sync.aligned.m8n8.x4.shared.b16 {%0,%1,%2,%3}, [%4];" \
        : "=r"((R)[0]), "=r"((R)[1]), "=r"((R)[2]), "=r"((R)[3]) : "r"(ADDR))

#define MMA16816(C, A, B0, B1) \
    asm volatile("mma.sync.aligned.m16n8k16.row.col.f32.bf16.bf16.f32 " \
        "{%0,%1,%2,%3}, {%4,%5,%6,%7}, {%8,%9}, {%0,%1,%2,%3};" \
        : "+f"((C)[0]), "+f"((C)[1]), "+f"((C)[2]), "+f"((C)[3]) \
        : "r"((A)[0]), "r"((A)[1]), "r"((A)[2]), "r"((A)[3]), "r"(B0), "r"(B1))

__device__ __forceinline__ void split_bf16(float x, unsigned short& h, unsigned short& l) {
    __nv_bfloat16 hb = __float2bfloat16(x);
    h = __bfloat16_as_ushort(hb);
    l = __bfloat16_as_ushort(__float2bfloat16(x - __bfloat162float(hb)));
}

// bn coefficient from sums: a = g*rsqrt(var+eps), c = b - a*mean
__device__ __forceinline__ void bn_coef(float sum, float sq, float gg, float bb,
                                        float& a, float& c) {
    const float inv = 1.0f / (float)NPTS;
    float m = sum * inv;
    float v = sq * inv - m * m;
    a = gg * rsqrtf(v + BNEPS);
    c = fmaf(-m, a, bb);
}

// ---------------- scratch ----------------
__device__ __align__(16) float g_y1 [NPTS*MIDF];
__device__ __align__(16) float g_y1a[NPTS*MIDF];   // lrelu(bn1(y1)) fp32
__device__ __align__(16) float g_x2 [NPTS*MIDF];
__device__ __align__(16) float g_y3 [NPTS*OUTF];
__device__ __align__(16) float g_ysc[NPTS*OUTF];

__device__ __align__(16) __nv_bfloat16 g_feat_hi[NPTS*INF], g_feat_lo[NPTS*INF];
__device__ __align__(16) __nv_bfloat16 g_wf_hi [NPTS*KPD], g_wf_lo [NPTS*KPD];
__device__ __align__(16) __nv_bfloat16 g_x2t_hi[NPTS*MIDF], g_x2t_lo[NPTS*MIDF];
__device__ __align__(16) __nv_bfloat16 g_w1t_hi[MIDF*INF],  g_w1t_lo[MIDF*INF];
__device__ __align__(16) __nv_bfloat16 g_kwt_hi[MIDF*KPD],  g_kwt_lo[MIDF*KPD];
__device__ __align__(16) __nv_bfloat16 g_w3t_hi[OUTF*MIDF], g_w3t_lo[OUTF*MIDF];
__device__ __align__(16) __nv_bfloat16 g_wst_hi[OUTF*INF],  g_wst_lo[OUTF*INF];

__device__ __align__(16) float g_sum1[MIDF], g_sq1[MIDF];
__device__ __align__(16) float g_sum2[MIDF], g_sq2[MIDF];
__device__ __align__(16) float g_sum3[OUTF], g_sq3[OUTF];
__device__ __align__(16) float g_sumS[OUTF], g_sqS[OUTF];

// ---------------- prep: stats zero + weight transposes + feat split -------
#define SEG1 (MIDF*INF)
#define SEG2 (MIDF*KPD)
#define SEG3 (OUTF*MIDF)
#define SEG4 (OUTF*INF)
#define PREP_TOT (SEG1+SEG2+SEG3+SEG4)
#define FEAT4_TOT (NPTS*INF/4)
__global__ void prep_kernel(const float* __restrict__ w1,
                            const float* __restrict__ kw,
                            const float* __restrict__ w3,
                            const float* __restrict__ ws,
                            const float* __restrict__ feat) {
    int i = blockIdx.x*blockDim.x + threadIdx.x;
    if (i < MIDF) { g_sum1[i]=0.f; g_sq1[i]=0.f; g_sum2[i]=0.f; g_sq2[i]=0.f; }
    if (i < OUTF) { g_sum3[i]=0.f; g_sq3[i]=0.f; g_sumS[i]=0.f; g_sqS[i]=0.f; }

    if (i < FEAT4_TOT) {
        float4 x = *(const float4*)&feat[(size_t)i*4];
        unsigned short h0,l0,h1,l1,h2,l2,h3,l3;
        split_bf16(x.x,h0,l0); split_bf16(x.y,h1,l1);
        split_bf16(x.z,h2,l2); split_bf16(x.w,h3,l3);
        uint2 hv = make_uint2(((uint32_t)h1<<16)|h0, ((uint32_t)h3<<16)|h2);
        uint2 lv = make_uint2(((uint32_t)l1<<16)|l0, ((uint32_t)l3<<16)|l2);
        *(uint2*)&g_feat_hi[(size_t)i*4] = hv;
        *(uint2*)&g_feat_lo[(size_t)i*4] = lv;
    }
    if (i < PREP_TOT) {
        const float* src; __nv_bfloat16 *dh, *dl; int K, N, idx;
        if (i < SEG1)                { src=w1; dh=g_w1t_hi; dl=g_w1t_lo; K=INF;  N=MIDF; idx=i; }
        else if (i < SEG1+SEG2)      { src=kw; dh=g_kwt_hi; dl=g_kwt_lo; K=KPD;  N=MIDF; idx=i-SEG1; }
        else if (i < SEG1+SEG2+SEG3) { src=w3; dh=g_w3t_hi; dl=g_w3t_lo; K=MIDF; N=OUTF; idx=i-SEG1-SEG2; }
        else                         { src=ws; dh=g_wst_hi; dl=g_wst_lo; K=INF;  N=OUTF; idx=i-SEG1-SEG2-SEG3; }
        int n = idx / K;
        int k = idx - n*K;
        float x = src[(size_t)k*N + n];
        unsigned short h, l;
        split_bf16(x, h, l);
        dh[idx] = __ushort_as_bfloat16(h);
        dl[idx] = __ushort_as_bfloat16(l);
    }
}

// y1a = lrelu(bn1(y1)) fp32; bn1 coeffs computed per block from sums
__global__ void y1a_kernel(const float* __restrict__ g1,
                           const float* __restrict__ b1) {
    __shared__ float sa[MIDF], sc[MIDF];
    int t = threadIdx.x;
    if (t < MIDF) bn_coef(g_sum1[t], g_sq1[t], g1[t], b1[t], sa[t], sc[t]);
    __syncthreads();

    int i = blockIdx.x*blockDim.x + t;               // float4 index
    const int total4 = NPTS*MIDF/4;
    if (i >= total4) return;
    int c0 = (i << 2) & (MIDF-1);
    float4 y = *(const float4*)&g_y1[(size_t)i*4];
    float4 o;
    o.x = fmaf(sa[c0+0], y.x, sc[c0+0]); o.x = fmaxf(o.x, SLOPE*o.x);
    o.y = fmaf(sa[c0+1], y.y, sc[c0+1]); o.y = fmaxf(o.y, SLOPE*o.y);
    o.z = fmaf(sa[c0+2], y.z, sc[c0+2]); o.z = fmaxf(o.z, SLOPE*o.z);
    o.w = fmaf(sa[c0+3], y.w, sc[c0+3]); o.w = fmaxf(o.w, SLOPE*o.w);
    *(float4*)&g_y1a[(size_t)i*4] = o;
}

// x2t = lrelu(bn2(x2)) -> bf16 hi/lo; bn2 coeffs per block
__global__ void split_x2t_kernel(const float* __restrict__ g2,
                                 const float* __restrict__ b2) {
    __shared__ float sa[MIDF], sc[MIDF];
    int t = threadIdx.x;
    if (t < MIDF) bn_coef(g_sum2[t], g_sq2[t], g2[t], b2[t], sa[t], sc[t]);
    __syncthreads();

    int i = blockIdx.x*blockDim.x + t;               // float4 index
    const int total4 = NPTS*MIDF/4;
    if (i >= total4) return;
    int c0 = (i << 2) & (MIDF-1);
    float4 x = *(const float4*)&g_x2[(size_t)i*4];
    float v0 = fmaf(sa[c0+0], x.x, sc[c0+0]); v0 = fmaxf(v0, SLOPE*v0);
    float v1 = fmaf(sa[c0+1], x.y, sc[c0+1]); v1 = fmaxf(v1, SLOPE*v1);
    float v2 = fmaf(sa[c0+2], x.z, sc[c0+2]); v2 = fmaxf(v2, SLOPE*v2);
    float v3 = fmaf(sa[c0+3], x.w, sc[c0+3]); v3 = fmaxf(v3, SLOPE*v3);
    unsigned short h0,l0,h1,l1,h2,l2,h3,l3;
    split_bf16(v0,h0,l0); split_bf16(v1,h1,l1);
    split_bf16(v2,h2,l2); split_bf16(v3,h3,l3);
    uint2 hv = make_uint2(((uint32_t)h1<<16)|h0, ((uint32_t)h3<<16)|h2);
    uint2 lv = make_uint2(((uint32_t)l1<<16)|l0, ((uint32_t)l3<<16)|l2);
    *(uint2*)&g_x2t_hi[(size_t)i*4] = hv;
    *(uint2*)&g_x2t_lo[(size_t)i*4] = lv;
}

// ---------------- mma.sync bf16 GEMM, cp.async double-buffered ------------
// (proven 416us config: 256 thr = 8 warps, 4m x 2n, tile 128x64, 2 stages)
#define KC   32
#define KCP  40
__global__ void __launch_bounds__(256) mma_gemm_kernel(int sel_base) {
    __shared__ __align__(16) __nv_bfloat16 sAh[2][128][KCP];
    __shared__ __align__(16) __nv_bfloat16 sAl[2][128][KCP];
    __shared__ __align__(16) __nv_bfloat16 sBh[2][64][KCP];
    __shared__ __align__(16) __nv_bfloat16 sBl[2][64][KCP];

    const int sel = sel_base + blockIdx.z;
    const __nv_bfloat16 *Ahi, *Alo, *Bhi, *Blo;
    float *C, *cS, *cQ;
    int Ktot, Ncol;
    switch (sel) {
        case 0:  Ahi=g_feat_hi; Alo=g_feat_lo; Bhi=g_w1t_hi;  Blo=g_w1t_lo;
                 C=g_y1;  cS=g_sum1; cQ=g_sq1; Ktot=INF;  Ncol=MIDF; break;
        case 1:  Ahi=g_wf_hi;   Alo=g_wf_lo;   Bhi=g_kwt_hi;  Blo=g_kwt_lo;
                 C=g_x2;  cS=g_sum2; cQ=g_sq2; Ktot=KPD;  Ncol=MIDF; break;
        case 2:  Ahi=g_x2t_hi;  Alo=g_x2t_lo;  Bhi=g_w3t_hi;  Blo=g_w3t_lo;
                 C=g_y3;  cS=g_sum3; cQ=g_sq3; Ktot=MIDF; Ncol=OUTF; break;
        default: Ahi=g_feat_hi; Alo=g_feat_lo; Bhi=g_wst_hi;  Blo=g_wst_lo;
                 C=g_ysc; cS=g_sumS; cQ=g_sqS; Ktot=INF;  Ncol=OUTF; break;
    }

    const int tid  = threadIdx.x;
    const int wid  = tid >> 5;
    const int lane = tid & 31;
    const int wr   = wid & 3;
    const int wc   = wid >> 2;
    const int row0 = blockIdx.x * 128;
    const int col0 = blockIdx.y * 64;

    auto issue = [&](int ck, int st) {
        #pragma unroll
        for (int j = 0; j < 2; j++) {
            int c   = tid + 256*j;
            int r   = c >> 2;
            int seg = c & 3;
            int grow = row0 + r;
            int sz = (grow < NPTS) ? 16 : 0;
            int gr = (grow < NPTS) ? grow : 0;
            const __nv_bfloat16* srcH = Ahi + (size_t)gr*Ktot + ck*KC + seg*8;
            const __nv_bfloat16* srcL = Alo + (size_t)gr*Ktot + ck*KC + seg*8;
            cp_async16(smem_u32(&sAh[st][r][seg*8]), srcH, sz);
            cp_async16(smem_u32(&sAl[st][r][seg*8]), srcL, sz);
        }
        {
            int r   = tid >> 2;
            int seg = tid & 3;
            const __nv_bfloat16* srcH = Bhi + (size_t)(col0 + r)*Ktot + ck*KC + seg*8;
            const __nv_bfloat16* srcL = Blo + (size_t)(col0 + r)*Ktot + ck*KC + seg*8;
            cp_async16(smem_u32(&sBh[st][r][seg*8]), srcH, 16);
            cp_async16(smem_u32(&sBl[st][r][seg*8]), srcL, 16);
        }
        CP_COMMIT();
    };

    float c[2][4][4];
    #pragma unroll
    for (int mb=0; mb<2; mb++)
        #pragma unroll
        for (int nb=0; nb<4; nb++)
            #pragma unroll
            for (int e=0; e<4; e++) c[mb][nb][e] = 0.f;

    const int nck = Ktot / KC;
    issue(0, 0);
    for (int ck = 0; ck < nck; ck++) {
        const int st = ck & 1;
        if (ck+1 < nck) { issue(ck+1, st^1); CP_WAIT1(); }
        else            { CP_WAIT0(); }
        __syncthreads();

        #pragma unroll
        for (int s = 0; s < 2; s++) {
            const int k0 = s*16;
            const int lrow = lane & 15;
            const int lcol = k0 + ((lane >> 4) << 3);
            uint32_t a_h[2][4], a_l[2][4], b_h[2][4], b_l[2][4];
            #pragma unroll
            for (int mb=0; mb<2; mb++) {
                int r = wr*32 + mb*16 + lrow;
                LDSM4(a_h[mb], smem_u32(&sAh[st][r][lcol]));
                LDSM4(a_l[mb], smem_u32(&sAl[st][r][lcol]));
            }
            #pragma unroll
            for (int g=0; g<2; g++) {
                int r = wc*32 + g*16 + lrow;
                LDSM4(b_h[g], smem_u32(&sBh[st][r][lcol]));
                LDSM4(b_l[g], smem_u32(&sBl[st][r][lcol]));
            }
            #pragma unroll
            for (int mb=0; mb<2; mb++) {
                #pragma unroll
                for (int nb=0; nb<4; nb++) {
                    int g = nb >> 1, h = nb & 1;
                    MMA16816(c[mb][nb], a_h[mb], b_h[g][h], b_h[g][h+2]);
                    MMA16816(c[mb][nb], a_h[mb], b_l[g][h], b_l[g][h+2]);
                    MMA16816(c[mb][nb], a_l[mb], b_h[g][h], b_h[g][h+2]);
                }
            }
        }
        __syncthreads();
    }

    #pragma unroll
    for (int nb=0; nb<4; nb++) {
        int ncol = col0 + wc*32 + nb*8 + (lane & 3)*2;
        float s0=0.f,q0=0.f,s1=0.f,q1=0.f;
        #pragma unroll
        for (int mb=0; mb<2; mb++) {
            int m0 = row0 + wr*32 + mb*16 + (lane >> 2);
            bool vA = m0 < NPTS, vB = (m0+8) < NPTS;
            float v0 = c[mb][nb][0], v1 = c[mb][nb][1];
            float v2 = c[mb][nb][2], v3 = c[mb][nb][3];
            if (vA) {
                *(float2*)&C[(size_t)m0*Ncol + ncol] = make_float2(v0, v1);
                s0 += v0; q0 += v0*v0; s1 += v1; q1 += v1*v1;
            }
            if (vB) {
                *(float2*)&C[(size_t)(m0+8)*Ncol + ncol] = make_float2(v2, v3);
                s0 += v2; q0 += v2*v2; s1 += v3; q1 += v3*v3;
            }
        }
        #pragma unroll
        for (int o=16;o>=4;o>>=1) {
            s0 += __shfl_xor_sync(0xffffffffu, s0, o);
            q0 += __shfl_xor_sync(0xffffffffu, q0, o);
            s1 += __shfl_xor_sync(0xffffffffu, s1, o);
            q1 += __shfl_xor_sync(0xffffffffu, q1, o);
        }
        if ((lane >> 2) == 0) {
            atomicAdd(&cS[ncol],   s0);
            atomicAdd(&cQ[ncol],   q0);
            atomicAdd(&cS[ncol+1], s1);
            atomicAdd(&cQ[ncol+1], q1);
        }
    }
}

// ---------------- KPConv gather: warp == point, 2 channels/thread ----------
// launch_bounds(256,5): cap regs at 51 for 5 blocks/SM (was 62 -> 4 blocks)
#define PPB 8
__global__ void __launch_bounds__(256, 5) kpconv_kernel(
                              const float* __restrict__ qpts,
                              const float* __restrict__ spts,
                              const int*   __restrict__ inds,
                              const float* __restrict__ kpts) {
    __shared__ __align__(16) float s_infl[PPB][HN*16];
    __shared__ __align__(16) float s_del[PPB][HN][3];
    __shared__ int   s_idx[PPB][HN];
    __shared__ float s_kp[KP*3];

    const int tid  = threadIdx.x;
    const int w    = tid >> 5;
    const int lane = tid & 31;
    const int n = blockIdx.x * PPB + w;

    if (tid < KP*3) s_kp[tid] = kpts[tid];

    {
        int idx = inds[n*HN + lane];
        s_idx[w][lane] = idx;
        s_del[w][lane][0] = spts[idx*3+0] - qpts[n*3+0];
        s_del[w][lane][1] = spts[idx*3+1] - qpts[n*3+1];
        s_del[w][lane][2] = spts[idx*3+2] - qpts[n*3+2];
    }
    __syncthreads();

    {
        int k  = lane & 15;
        int hb = (lane >> 4) << 4;
        bool valid = (k < KP);
        float kx=0.f, ky=0.f, kz=0.f;
        if (valid) { kx = s_kp[k*3+0]; ky = s_kp[k*3+1]; kz = s_kp[k*3+2]; }
        #pragma unroll 4
        for (int j = 0; j < 16; j++) {
            int h = hb + j;
            float val = 0.f;
            if (valid) {
                float dx = s_del[w][h][0] - kx;
                float dy = s_del[w][h][1] - ky;
                float dz = s_del[w][h][2] - kz;
                float sq = fmaf(dx,dx,fmaf(dy,dy,dz*dz));
                float dist = sqrtf(fmaxf(sq, 1e-12f));
                val = fmaxf(0.f, 1.f - dist*(1.f/KPEXT));
            }
            s_infl[w][h*16 + k] = val;
        }
    }
    __syncwarp();

    const int ch = lane*2;
    ull acc0[8], acc1[8];
    #pragma unroll
    for (int m=0;m<8;m++) { acc0[m]=0ull; acc1[m]=0ull; }

    const float* inflp = s_infl[w];
    #pragma unroll 2
    for (int h = 0; h < HN; h++) {
        int idx = s_idx[w][h];
        float2 v = *(const float2*)&g_y1a[(size_t)idx*MIDF + ch];
        ull vx2 = pack2(v.x, v.x);
        ull vy2 = pack2(v.y, v.y);

        const ulonglong2* fp = (const ulonglong2*)&inflp[h*16];
        ulonglong2 fA = fp[0], fB = fp[1], fC = fp[2], fD = fp[3];
        ull fk2[8] = {fA.x,fA.y,fB.x,fB.y,fC.x,fC.y,fD.x,fD.y};
        #pragma unroll
        for (int m=0;m<8;m++) {
            ffma2(acc0[m], vx2, fk2[m]);
            ffma2(acc1[m], vy2, fk2[m]);
        }
    }

    size_t base = (size_t)n*KPD + ch;
    #pragma unroll
    for (int m=0;m<8;m++) {
        float x0,x1,y0,y1;
        unpack2(acc0[m], x0, x1);
        unpack2(acc1[m], y0, y1);
        {
            unsigned short hx,lx,hy,ly;
            split_bf16(x0, hx, lx);
            split_bf16(y0, hy, ly);
            *(uint32_t*)&g_wf_hi[base + (size_t)(2*m)*MIDF] = ((uint32_t)hy<<16)|hx;
            *(uint32_t*)&g_wf_lo[base + (size_t)(2*m)*MIDF] = ((uint32_t)ly<<16)|lx;
        }
        if (2*m+1 < KP) {
            unsigned short hx,lx,hy,ly;
            split_bf16(x1, hx, lx);
            split_bf16(y1, hy, ly);
            *(uint32_t*)&g_wf_hi[base + (size_t)(2*m+1)*MIDF] = ((uint32_t)hy<<16)|hx;
            *(uint32_t*)&g_wf_lo[base + (size_t)(2*m+1)*MIDF] = ((uint32_t)ly<<16)|lx;
        }
    }
}

// ---------------- final: bn3/bnS coeffs inlined ----------------
__global__ void final_kernel(const float* __restrict__ g3,
                             const float* __restrict__ b3,
                             const float* __restrict__ gs,
                             const float* __restrict__ bs,
                             float* __restrict__ out) {
    __shared__ float sa3[OUTF], sc3[OUTF], saS[OUTF], scS[OUTF];
    int t = threadIdx.x;
    bn_coef(g_sum3[t], g_sq3[t], g3[t], b3[t], sa3[t], sc3[t]);
    bn_coef(g_sumS[t], g_sqS[t], gs[t], bs[t], saS[t], scS[t]);
    __syncthreads();

    int i = blockIdx.x*blockDim.x + t;               // float4 index
    const int total4 = NPTS*OUTF/4;
    if (i >= total4) return;
    int c0 = (i << 2) & (OUTF-1);
    float4 y = *(const float4*)&g_y3[(size_t)i*4];
    float4 s = *(const float4*)&g_ysc[(size_t)i*4];
    float vy[4] = {y.x,y.y,y.z,y.w};
    float vs[4] = {s.x,s.y,s.z,s.w};
    float vo[4];
    #pragma unroll
    for (int j=0;j<4;j++) {
        int c = c0 + j;
        float a = fmaf(sa3[c], vy[j], sc3[c]); a = fmaxf(a, SLOPE*a);
        float b = fmaf(saS[c], vs[j], scS[c]); b = fmaxf(b, SLOPE*b);
        float r = a + b;
        vo[j] = fmaxf(r, SLOPE*r);
    }
    *(float4*)&out[(size_t)i*4] = make_float4(vo[0],vo[1],vo[2],vo[3]);
}

// ---------------- launcher ----------------
extern "C" void kernel_launch(void* const* d_in, const int* in_sizes, int n_in,
                              void* d_out, int out_size) {
    const float* q    = (const float*)d_in[0];
    const float* s    = (const float*)d_in[1];
    const int*   inds = (const int*)  d_in[2];
    const float* feat = (const float*)d_in[3];
    const float* kp   = (const float*)d_in[4];
    const float* w1   = (const float*)d_in[5];
    const float* g1   = (const float*)d_in[6];
    const float* b1   = (const float*)d_in[7];
    const float* kw   = (const float*)d_in[8];
    const float* g2   = (const float*)d_in[9];
    const float* b2   = (const float*)d_in[10];
    const float* w3   = (const float*)d_in[11];
    const float* g3   = (const float*)d_in[12];
    const float* b3   = (const float*)d_in[13];
    const float* ws   = (const float*)d_in[14];
    const float* gs   = (const float*)d_in[15];
    const float* bs   = (const float*)d_in[16];
    float* out = (float*)d_out;

    const int MT = (NPTS + 127) / 128;   // 391 row tiles

    // 1: stats zero + weight split/transpose + feat split
    prep_kernel<<<(FEAT4_TOT + 255)/256, 256>>>(w1, kw, w3, ws, feat);

    // 2: conv1  y1 = feat @ w1
    mma_gemm_kernel<<<dim3(MT,1,1), 256>>>(0);

    // 3: y1a = lrelu(bn1(y1)) fp32  (bn1 coeffs inlined)
    y1a_kernel<<<(NPTS*MIDF/4 + 255)/256, 256>>>(g1, b1);

    // 4: KPConv gather -> wf (bf16 hi/lo)
    kpconv_kernel<<<NPTS/PPB, 256>>>(q, s, inds, kp);

    // 5: conv2  x2 = wf @ kw
    mma_gemm_kernel<<<dim3(MT,1,1), 256>>>(1);

    // 6: x2t = lrelu(bn2(x2)) -> bf16 hi/lo  (bn2 coeffs inlined)
    split_x2t_kernel<<<(NPTS*MIDF/4 + 255)/256, 256>>>(g2, b2);

    // 7: conv3 (z=0) + shortcut (z=1)
    mma_gemm_kernel<<<dim3(MT,4,2), 256>>>(2);

    // 8: output  (bn3/bnS coeffs inlined)
    final_kernel<<<(NPTS*OUTF/4 + 255)/256, 256>>>(g3, b3, gs, bs, out);
}

// round 15
// speedup vs baseline: 1.0460x; 1.0460x over previous
#include <cuda_runtime.h>
#include <cuda_bf16.h>
#include <cstdint>

// ---------------- problem constants ----------------
#define NPTS  50000
#define HN    32
#define INF   128
#define MIDF  64
#define OUTF  256
#define KP    15
#define KPD   (KP*MIDF)      // 960
#define KPEXT 0.48f
#define BNEPS 1e-6f
#define SLOPE 0.1f

typedef unsigned long long ull;

// ---------------- helpers ----------------
__device__ __forceinline__ ull pack2(float x, float y) {
    ull r; asm("mov.b64 %0, {%1, %2};" : "=l"(r) : "f"(x), "f"(y)); return r;
}
__device__ __forceinline__ void unpack2(ull v, float& x, float& y) {
    asm("mov.b64 {%0, %1}, %2;" : "=f"(x), "=f"(y) : "l"(v));
}
__device__ __forceinline__ void ffma2(ull& d, ull a, ull b) {
    asm("fma.rn.f32x2 %0, %1, %2, %0;" : "+l"(d) : "l"(a), "l"(b));
}
__device__ __forceinline__ uint32_t smem_u32(const void* p) {
    uint32_t a;
    asm("{ .reg .u64 t; cvta.to.shared.u64 t, %1; cvt.u32.u64 %0, t; }" : "=r"(a) : "l"(p));
    return a;
}
__device__ __forceinline__ void cp_async16(uint32_t dst, const void* src, int szbytes) {
    asm volatile("cp.async.cg.shared.global [%0], [%1], 16, %2;"
                 :: "r"(dst), "l"(src), "r"(szbytes));
}
#define CP_COMMIT() asm volatile("cp.async.commit_group;" ::: "memory")
#define CP_WAIT1()  asm volatile("cp.async.wait_group 1;" ::: "memory")
#define CP_WAIT0()  asm volatile("cp.async.wait_group 0;" ::: "memory")

#define LDSM4(R, ADDR) \
    asm volatile("ldmatrix.sync.aligned.m8n8.x4.shared.b16 {%0,%1,%2,%3}, [%4];" \
        : "=r"((R)[0]), "=r"((R)[1]), "=r"((R)[2]), "=r"((R)[3]) : "r"(ADDR))

#define MMA16816(C, A, B0, B1) \
    asm volatile("mma.sync.aligned.m16n8k16.row.col.f32.bf16.bf16.f32 " \
        "{%0,%1,%2,%3}, {%4,%5,%6,%7}, {%8,%9}, {%0,%1,%2,%3};" \
        : "+f"((C)[0]), "+f"((C)[1]), "+f"((C)[2]), "+f"((C)[3]) \
        : "r"((A)[0]), "r"((A)[1]), "r"((A)[2]), "r"((A)[3]), "r"(B0), "r"(B1))

__device__ __forceinline__ void split_bf16(float x, unsigned short& h, unsigned short& l) {
    __nv_bfloat16 hb = __float2bfloat16(x);
    h = __bfloat16_as_ushort(hb);
    l = __bfloat16_as_ushort(__float2bfloat16(x - __bfloat162float(hb)));
}

// bn coefficient from sums: a = g*rsqrt(var+eps), c = b - a*mean
__device__ __forceinline__ void bn_coef(float sum, float sq, float gg, float bb,
                                        float& a, float& c) {
    const float inv = 1.0f / (float)NPTS;
    float m = sum * inv;
    float v = sq * inv - m * m;
    a = gg * rsqrtf(v + BNEPS);
    c = fmaf(-m, a, bb);
}

// ---------------- scratch ----------------
__device__ __align__(16) float g_y1 [NPTS*MIDF];
__device__ __align__(16) float g_y1a[NPTS*MIDF];   // lrelu(bn1(y1)) fp32
__device__ __align__(16) float g_x2 [NPTS*MIDF];
__device__ __align__(16) float g_y3 [NPTS*OUTF];
__device__ __align__(16) float g_ysc[NPTS*OUTF];

__device__ __align__(16) __nv_bfloat16 g_feat_hi[NPTS*INF], g_feat_lo[NPTS*INF];
__device__ __align__(16) __nv_bfloat16 g_wf_hi [NPTS*KPD], g_wf_lo [NPTS*KPD];
__device__ __align__(16) __nv_bfloat16 g_x2t_hi[NPTS*MIDF], g_x2t_lo[NPTS*MIDF];
__device__ __align__(16) __nv_bfloat16 g_w1t_hi[MIDF*INF],  g_w1t_lo[MIDF*INF];
__device__ __align__(16) __nv_bfloat16 g_kwt_hi[MIDF*KPD],  g_kwt_lo[MIDF*KPD];
__device__ __align__(16) __nv_bfloat16 g_w3t_hi[OUTF*MIDF], g_w3t_lo[OUTF*MIDF];
__device__ __align__(16) __nv_bfloat16 g_wst_hi[OUTF*INF],  g_wst_lo[OUTF*INF];

__device__ __align__(16) float g_sum1[MIDF], g_sq1[MIDF];
__device__ __align__(16) float g_sum2[MIDF], g_sq2[MIDF];
__device__ __align__(16) float g_sum3[OUTF], g_sq3[OUTF];
__device__ __align__(16) float g_sumS[OUTF], g_sqS[OUTF];

// ---------------- prep: stats zero + weight transposes + feat split -------
#define SEG1 (MIDF*INF)
#define SEG2 (MIDF*KPD)
#define SEG3 (OUTF*MIDF)
#define SEG4 (OUTF*INF)
#define PREP_TOT (SEG1+SEG2+SEG3+SEG4)
#define FEAT4_TOT (NPTS*INF/4)
__global__ void prep_kernel(const float* __restrict__ w1,
                            const float* __restrict__ kw,
                            const float* __restrict__ w3,
                            const float* __restrict__ ws,
                            const float* __restrict__ feat) {
    int i = blockIdx.x*blockDim.x + threadIdx.x;
    if (i < MIDF) { g_sum1[i]=0.f; g_sq1[i]=0.f; g_sum2[i]=0.f; g_sq2[i]=0.f; }
    if (i < OUTF) { g_sum3[i]=0.f; g_sq3[i]=0.f; g_sumS[i]=0.f; g_sqS[i]=0.f; }

    if (i < FEAT4_TOT) {
        float4 x = *(const float4*)&feat[(size_t)i*4];
        unsigned short h0,l0,h1,l1,h2,l2,h3,l3;
        split_bf16(x.x,h0,l0); split_bf16(x.y,h1,l1);
        split_bf16(x.z,h2,l2); split_bf16(x.w,h3,l3);
        uint2 hv = make_uint2(((uint32_t)h1<<16)|h0, ((uint32_t)h3<<16)|h2);
        uint2 lv = make_uint2(((uint32_t)l1<<16)|l0, ((uint32_t)l3<<16)|l2);
        *(uint2*)&g_feat_hi[(size_t)i*4] = hv;
        *(uint2*)&g_feat_lo[(size_t)i*4] = lv;
    }
    if (i < PREP_TOT) {
        const float* src; __nv_bfloat16 *dh, *dl; int K, N, idx;
        if (i < SEG1)                { src=w1; dh=g_w1t_hi; dl=g_w1t_lo; K=INF;  N=MIDF; idx=i; }
        else if (i < SEG1+SEG2)      { src=kw; dh=g_kwt_hi; dl=g_kwt_lo; K=KPD;  N=MIDF; idx=i-SEG1; }
        else if (i < SEG1+SEG2+SEG3) { src=w3; dh=g_w3t_hi; dl=g_w3t_lo; K=MIDF; N=OUTF; idx=i-SEG1-SEG2; }
        else                         { src=ws; dh=g_wst_hi; dl=g_wst_lo; K=INF;  N=OUTF; idx=i-SEG1-SEG2-SEG3; }
        int n = idx / K;
        int k = idx - n*K;
        float x = src[(size_t)k*N + n];
        unsigned short h, l;
        split_bf16(x, h, l);
        dh[idx] = __ushort_as_bfloat16(h);
        dl[idx] = __ushort_as_bfloat16(l);
    }
}

// y1a = lrelu(bn1(y1)) fp32; bn1 coeffs computed per block from sums
__global__ void y1a_kernel(const float* __restrict__ g1,
                           const float* __restrict__ b1) {
    __shared__ float sa[MIDF], sc[MIDF];
    int t = threadIdx.x;
    if (t < MIDF) bn_coef(g_sum1[t], g_sq1[t], g1[t], b1[t], sa[t], sc[t]);
    __syncthreads();

    int i = blockIdx.x*blockDim.x + t;               // float4 index
    const int total4 = NPTS*MIDF/4;
    if (i >= total4) return;
    int c0 = (i << 2) & (MIDF-1);
    float4 y = *(const float4*)&g_y1[(size_t)i*4];
    float4 o;
    o.x = fmaf(sa[c0+0], y.x, sc[c0+0]); o.x = fmaxf(o.x, SLOPE*o.x);
    o.y = fmaf(sa[c0+1], y.y, sc[c0+1]); o.y = fmaxf(o.y, SLOPE*o.y);
    o.z = fmaf(sa[c0+2], y.z, sc[c0+2]); o.z = fmaxf(o.z, SLOPE*o.z);
    o.w = fmaf(sa[c0+3], y.w, sc[c0+3]); o.w = fmaxf(o.w, SLOPE*o.w);
    *(float4*)&g_y1a[(size_t)i*4] = o;
}

// x2t = lrelu(bn2(x2)) -> bf16 hi/lo; bn2 coeffs per block
__global__ void split_x2t_kernel(const float* __restrict__ g2,
                                 const float* __restrict__ b2) {
    __shared__ float sa[MIDF], sc[MIDF];
    int t = threadIdx.x;
    if (t < MIDF) bn_coef(g_sum2[t], g_sq2[t], g2[t], b2[t], sa[t], sc[t]);
    __syncthreads();

    int i = blockIdx.x*blockDim.x + t;               // float4 index
    const int total4 = NPTS*MIDF/4;
    if (i >= total4) return;
    int c0 = (i << 2) & (MIDF-1);
    float4 x = *(const float4*)&g_x2[(size_t)i*4];
    float v0 = fmaf(sa[c0+0], x.x, sc[c0+0]); v0 = fmaxf(v0, SLOPE*v0);
    float v1 = fmaf(sa[c0+1], x.y, sc[c0+1]); v1 = fmaxf(v1, SLOPE*v1);
    float v2 = fmaf(sa[c0+2], x.z, sc[c0+2]); v2 = fmaxf(v2, SLOPE*v2);
    float v3 = fmaf(sa[c0+3], x.w, sc[c0+3]); v3 = fmaxf(v3, SLOPE*v3);
    unsigned short h0,l0,h1,l1,h2,l2,h3,l3;
    split_bf16(v0,h0,l0); split_bf16(v1,h1,l1);
    split_bf16(v2,h2,l2); split_bf16(v3,h3,l3);
    uint2 hv = make_uint2(((uint32_t)h1<<16)|h0, ((uint32_t)h3<<16)|h2);
    uint2 lv = make_uint2(((uint32_t)l1<<16)|l0, ((uint32_t)l3<<16)|l2);
    *(uint2*)&g_x2t_hi[(size_t)i*4] = hv;
    *(uint2*)&g_x2t_lo[(size_t)i*4] = lv;
}

// ---------------- mma.sync bf16 GEMM, cp.async double-buffered ------------
// (proven config: 256 thr = 8 warps, 4m x 2n, tile 128x64, 2 stages)
#define KC   32
#define KCP  40
__global__ void __launch_bounds__(256) mma_gemm_kernel(int sel_base) {
    __shared__ __align__(16) __nv_bfloat16 sAh[2][128][KCP];
    __shared__ __align__(16) __nv_bfloat16 sAl[2][128][KCP];
    __shared__ __align__(16) __nv_bfloat16 sBh[2][64][KCP];
    __shared__ __align__(16) __nv_bfloat16 sBl[2][64][KCP];

    const int sel = sel_base + blockIdx.z;
    const __nv_bfloat16 *Ahi, *Alo, *Bhi, *Blo;
    float *C, *cS, *cQ;
    int Ktot, Ncol;
    switch (sel) {
        case 0:  Ahi=g_feat_hi; Alo=g_feat_lo; Bhi=g_w1t_hi;  Blo=g_w1t_lo;
                 C=g_y1;  cS=g_sum1; cQ=g_sq1; Ktot=INF;  Ncol=MIDF; break;
        case 1:  Ahi=g_wf_hi;   Alo=g_wf_lo;   Bhi=g_kwt_hi;  Blo=g_kwt_lo;
                 C=g_x2;  cS=g_sum2; cQ=g_sq2; Ktot=KPD;  Ncol=MIDF; break;
        case 2:  Ahi=g_x2t_hi;  Alo=g_x2t_lo;  Bhi=g_w3t_hi;  Blo=g_w3t_lo;
                 C=g_y3;  cS=g_sum3; cQ=g_sq3; Ktot=MIDF; Ncol=OUTF; break;
        default: Ahi=g_feat_hi; Alo=g_feat_lo; Bhi=g_wst_hi;  Blo=g_wst_lo;
                 C=g_ysc; cS=g_sumS; cQ=g_sqS; Ktot=INF;  Ncol=OUTF; break;
    }

    const int tid  = threadIdx.x;
    const int wid  = tid >> 5;
    const int lane = tid & 31;
    const int wr   = wid & 3;
    const int wc   = wid >> 2;
    const int row0 = blockIdx.x * 128;
    const int col0 = blockIdx.y * 64;

    auto issue = [&](int ck, int st) {
        #pragma unroll
        for (int j = 0; j < 2; j++) {
            int c   = tid + 256*j;
            int r   = c >> 2;
            int seg = c & 3;
            int grow = row0 + r;
            int sz = (grow < NPTS) ? 16 : 0;
            int gr = (grow < NPTS) ? grow : 0;
            const __nv_bfloat16* srcH = Ahi + (size_t)gr*Ktot + ck*KC + seg*8;
            const __nv_bfloat16* srcL = Alo + (size_t)gr*Ktot + ck*KC + seg*8;
            cp_async16(smem_u32(&sAh[st][r][seg*8]), srcH, sz);
            cp_async16(smem_u32(&sAl[st][r][seg*8]), srcL, sz);
        }
        {
            int r   = tid >> 2;
            int seg = tid & 3;
            const __nv_bfloat16* srcH = Bhi + (size_t)(col0 + r)*Ktot + ck*KC + seg*8;
            const __nv_bfloat16* srcL = Blo + (size_t)(col0 + r)*Ktot + ck*KC + seg*8;
            cp_async16(smem_u32(&sBh[st][r][seg*8]), srcH, 16);
            cp_async16(smem_u32(&sBl[st][r][seg*8]), srcL, 16);
        }
        CP_COMMIT();
    };

    float c[2][4][4];
    #pragma unroll
    for (int mb=0; mb<2; mb++)
        #pragma unroll
        for (int nb=0; nb<4; nb++)
            #pragma unroll
            for (int e=0; e<4; e++) c[mb][nb][e] = 0.f;

    const int nck = Ktot / KC;
    issue(0, 0);
    for (int ck = 0; ck < nck; ck++) {
        const int st = ck & 1;
        if (ck+1 < nck) { issue(ck+1, st^1); CP_WAIT1(); }
        else            { CP_WAIT0(); }
        __syncthreads();

        #pragma unroll
        for (int s = 0; s < 2; s++) {
            const int k0 = s*16;
            const int lrow = lane & 15;
            const int lcol = k0 + ((lane >> 4) << 3);
            uint32_t a_h[2][4], a_l[2][4], b_h[2][4], b_l[2][4];
            #pragma unroll
            for (int mb=0; mb<2; mb++) {
                int r = wr*32 + mb*16 + lrow;
                LDSM4(a_h[mb], smem_u32(&sAh[st][r][lcol]));
                LDSM4(a_l[mb], smem_u32(&sAl[st][r][lcol]));
            }
            #pragma unroll
            for (int g=0; g<2; g++) {
                int r = wc*32 + g*16 + lrow;
                LDSM4(b_h[g], smem_u32(&sBh[st][r][lcol]));
                LDSM4(b_l[g], smem_u32(&sBl[st][r][lcol]));
            }
            #pragma unroll
            for (int mb=0; mb<2; mb++) {
                #pragma unroll
                for (int nb=0; nb<4; nb++) {
                    int g = nb >> 1, h = nb & 1;
                    MMA16816(c[mb][nb], a_h[mb], b_h[g][h], b_h[g][h+2]);
                    MMA16816(c[mb][nb], a_h[mb], b_l[g][h], b_l[g][h+2]);
                    MMA16816(c[mb][nb], a_l[mb], b_h[g][h], b_h[g][h+2]);
                }
            }
        }
        __syncthreads();
    }

    #pragma unroll
    for (int nb=0; nb<4; nb++) {
        int ncol = col0 + wc*32 + nb*8 + (lane & 3)*2;
        float s0=0.f,q0=0.f,s1=0.f,q1=0.f;
        #pragma unroll
        for (int mb=0; mb<2; mb++) {
            int m0 = row0 + wr*32 + mb*16 + (lane >> 2);
            bool vA = m0 < NPTS, vB = (m0+8) < NPTS;
            float v0 = c[mb][nb][0], v1 = c[mb][nb][1];
            float v2 = c[mb][nb][2], v3 = c[mb][nb][3];
            if (vA) {
                *(float2*)&C[(size_t)m0*Ncol + ncol] = make_float2(v0, v1);
                s0 += v0; q0 += v0*v0; s1 += v1; q1 += v1*v1;
            }
            if (vB) {
                *(float2*)&C[(size_t)(m0+8)*Ncol + ncol] = make_float2(v2, v3);
                s0 += v2; q0 += v2*v2; s1 += v3; q1 += v3*v3;
            }
        }
        #pragma unroll
        for (int o=16;o>=4;o>>=1) {
            s0 += __shfl_xor_sync(0xffffffffu, s0, o);
            q0 += __shfl_xor_sync(0xffffffffu, q0, o);
            s1 += __shfl_xor_sync(0xffffffffu, s1, o);
            q1 += __shfl_xor_sync(0xffffffffu, q1, o);
        }
        if ((lane >> 2) == 0) {
            atomicAdd(&cS[ncol],   s0);
            atomicAdd(&cQ[ncol],   q0);
            atomicAdd(&cS[ncol+1], s1);
            atomicAdd(&cQ[ncol+1], q1);
        }
    }
}

// ---------------- KPConv gather: warp == point, 2 channels/thread ----------
// (proven 115us config: plain launch_bounds(256), 62 regs, 4 blocks/SM)
#define PPB 8
__global__ void __launch_bounds__(256) kpconv_kernel(
                              const float* __restrict__ qpts,
                              const float* __restrict__ spts,
                              const int*   __restrict__ inds,
                              const float* __restrict__ kpts) {
    __shared__ __align__(16) float s_infl[PPB][HN*16];
    __shared__ __align__(16) float s_del[PPB][HN][3];
    __shared__ int   s_idx[PPB][HN];
    __shared__ float s_kp[KP*3];

    const int tid  = threadIdx.x;
    const int w    = tid >> 5;
    const int lane = tid & 31;
    const int n = blockIdx.x * PPB + w;

    if (tid < KP*3) s_kp[tid] = kpts[tid];

    {
        int idx = inds[n*HN + lane];
        s_idx[w][lane] = idx;
        s_del[w][lane][0] = spts[idx*3+0] - qpts[n*3+0];
        s_del[w][lane][1] = spts[idx*3+1] - qpts[n*3+1];
        s_del[w][lane][2] = spts[idx*3+2] - qpts[n*3+2];
    }
    __syncthreads();

    {
        int k  = lane & 15;
        int hb = (lane >> 4) << 4;
        bool valid = (k < KP);
        float kx=0.f, ky=0.f, kz=0.f;
        if (valid) { kx = s_kp[k*3+0]; ky = s_kp[k*3+1]; kz = s_kp[k*3+2]; }
        #pragma unroll 4
        for (int j = 0; j < 16; j++) {
            int h = hb + j;
            float val = 0.f;
            if (valid) {
                float dx = s_del[w][h][0] - kx;
                float dy = s_del[w][h][1] - ky;
                float dz = s_del[w][h][2] - kz;
                float sq = fmaf(dx,dx,fmaf(dy,dy,dz*dz));
                float dist = sqrtf(fmaxf(sq, 1e-12f));
                val = fmaxf(0.f, 1.f - dist*(1.f/KPEXT));
            }
            s_infl[w][h*16 + k] = val;
        }
    }
    __syncwarp();

    const int ch = lane*2;
    ull acc0[8], acc1[8];
    #pragma unroll
    for (int m=0;m<8;m++) { acc0[m]=0ull; acc1[m]=0ull; }

    const float* inflp = s_infl[w];
    #pragma unroll 2
    for (int h = 0; h < HN; h++) {
        int idx = s_idx[w][h];
        float2 v = *(const float2*)&g_y1a[(size_t)idx*MIDF + ch];
        ull vx2 = pack2(v.x, v.x);
        ull vy2 = pack2(v.y, v.y);

        const ulonglong2* fp = (const ulonglong2*)&inflp[h*16];
        ulonglong2 fA = fp[0], fB = fp[1], fC = fp[2], fD = fp[3];
        ull fk2[8] = {fA.x,fA.y,fB.x,fB.y,fC.x,fC.y,fD.x,fD.y};
        #pragma unroll
        for (int m=0;m<8;m++) {
            ffma2(acc0[m], vx2, fk2[m]);
            ffma2(acc1[m], vy2, fk2[m]);
        }
    }

    size_t base = (size_t)n*KPD + ch;
    #pragma unroll
    for (int m=0;m<8;m++) {
        float x0,x1,y0,y1;
        unpack2(acc0[m], x0, x1);
        unpack2(acc1[m], y0, y1);
        {
            unsigned short hx,lx,hy,ly;
            split_bf16(x0, hx, lx);
            split_bf16(y0, hy, ly);
            *(uint32_t*)&g_wf_hi[base + (size_t)(2*m)*MIDF] = ((uint32_t)hy<<16)|hx;
            *(uint32_t*)&g_wf_lo[base + (size_t)(2*m)*MIDF] = ((uint32_t)ly<<16)|lx;
        }
        if (2*m+1 < KP) {
            unsigned short hx,lx,hy,ly;
            split_bf16(x1, hx, lx);
            split_bf16(y1, hy, ly);
            *(uint32_t*)&g_wf_hi[base + (size_t)(2*m+1)*MIDF] = ((uint32_t)hy<<16)|hx;
            *(uint32_t*)&g_wf_lo[base + (size_t)(2*m+1)*MIDF] = ((uint32_t)ly<<16)|lx;
        }
    }
}

// ---------------- final: bn3/bnS coeffs inlined ----------------
__global__ void final_kernel(const float* __restrict__ g3,
                             const float* __restrict__ b3,
                             const float* __restrict__ gs,
                             const float* __restrict__ bs,
                             float* __restrict__ out) {
    __shared__ float sa3[OUTF], sc3[OUTF], saS[OUTF], scS[OUTF];
    int t = threadIdx.x;
    bn_coef(g_sum3[t], g_sq3[t], g3[t], b3[t], sa3[t], sc3[t]);
    bn_coef(g_sumS[t], g_sqS[t], gs[t], bs[t], saS[t], scS[t]);
    __syncthreads();

    int i = blockIdx.x*blockDim.x + t;               // float4 index
    const int total4 = NPTS*OUTF/4;
    if (i >= total4) return;
    int c0 = (i << 2) & (OUTF-1);
    float4 y = *(const float4*)&g_y3[(size_t)i*4];
    float4 s = *(const float4*)&g_ysc[(size_t)i*4];
    float vy[4] = {y.x,y.y,y.z,y.w};
    float vs[4] = {s.x,s.y,s.z,s.w};
    float vo[4];
    #pragma unroll
    for (int j=0;j<4;j++) {
        int c = c0 + j;
        float a = fmaf(sa3[c], vy[j], sc3[c]); a = fmaxf(a, SLOPE*a);
        float b = fmaf(saS[c], vs[j], scS[c]); b = fmaxf(b, SLOPE*b);
        float r = a + b;
        vo[j] = fmaxf(r, SLOPE*r);
    }
    *(float4*)&out[(size_t)i*4] = make_float4(vo[0],vo[1],vo[2],vo[3]);
}

// ---------------- launcher ----------------
extern "C" void kernel_launch(void* const* d_in, const int* in_sizes, int n_in,
                              void* d_out, int out_size) {
    const float* q    = (const float*)d_in[0];
    const float* s    = (const float*)d_in[1];
    const int*   inds = (const int*)  d_in[2];
    const float* feat = (const float*)d_in[3];
    const float* kp   = (const float*)d_in[4];
    const float* w1   = (const float*)d_in[5];
    const float* g1   = (const float*)d_in[6];
    const float* b1   = (const float*)d_in[7];
    const float* kw   = (const float*)d_in[8];
    const float* g2   = (const float*)d_in[9];
    const float* b2   = (const float*)d_in[10];
    const float* w3   = (const float*)d_in[11];
    const float* g3   = (const float*)d_in[12];
    const float* b3   = (const float*)d_in[13];
    const float* ws   = (const float*)d_in[14];
    const float* gs   = (const float*)d_in[15];
    const float* bs   = (const float*)d_in[16];
    float* out = (float*)d_out;

    const int MT = (NPTS + 127) / 128;   // 391 row tiles

    // 1: stats zero + weight split/transpose + feat split
    prep_kernel<<<(FEAT4_TOT + 255)/256, 256>>>(w1, kw, w3, ws, feat);

    // 2: conv1  y1 = feat @ w1
    mma_gemm_kernel<<<dim3(MT,1,1), 256>>>(0);

    // 3: y1a = lrelu(bn1(y1)) fp32  (bn1 coeffs inlined)
    y1a_kernel<<<(NPTS*MIDF/4 + 255)/256, 256>>>(g1, b1);

    // 4: KPConv gather -> wf (bf16 hi/lo)
    kpconv_kernel<<<NPTS/PPB, 256>>>(q, s, inds, kp);

    // 5: conv2  x2 = wf @ kw
    mma_gemm_kernel<<<dim3(MT,1,1), 256>>>(1);

    // 6: x2t = lrelu(bn2(x2)) -> bf16 hi/lo  (bn2 coeffs inlined)
    split_x2t_kernel<<<(NPTS*MIDF/4 + 255)/256, 256>>>(g2, b2);

    // 7: conv3 (z=0) + shortcut (z=1)
    mma_gemm_kernel<<<dim3(MT,4,2), 256>>>(2);

    // 8: output  (bn3/bnS coeffs inlined)
    final_kernel<<<(NPTS*OUTF/4 + 255)/256, 256>>>(g3, b3, gs, bs, out);
}